// round 2
// baseline (speedup 1.0000x reference)
#include <cuda_runtime.h>
#include <cuda_bf16.h>

#define B_   64
#define D_   25000
#define K_   16
#define H_   128
#define E_   256
#define Z_   32
#define TD   32          // d-tile per CTA
#define THR  256

// ---------------- device scratch (static: no allocations allowed) ----------------
__device__ float g_G[D_ * H_];       // 12.8 MB: precomputed per-feature layer-1 term
__device__ float g_c[B_ * K_];       // pooled c[b,k]
__device__ float g_a1[B_ * E_];      // encoder hidden

// ---------------- f32x2 helpers ----------------
__device__ __forceinline__ unsigned long long pk2(float lo, float hi) {
    unsigned long long r;
    asm("mov.b64 %0, {%1, %2};" : "=l"(r) : "f"(lo), "f"(hi));
    return r;
}
__device__ __forceinline__ void fma2(unsigned long long& d,
                                     unsigned long long a, unsigned long long b) {
    asm("fma.rn.f32x2 %0, %1, %2, %3;" : "=l"(d) : "l"(a), "l"(b), "l"(d));
}
__device__ __forceinline__ float2 unpk(unsigned long long v) {
    float2 r;
    asm("mov.b64 {%0, %1}, %2;" : "=f"(r.x), "=f"(r.y) : "l"(v));
    return r;
}

// ---------------- K1: G[d,h] = b1 + feat_emb[d]@W1[1:17] + feat_bias[d]*W1[17]; zero g_c ----
__global__ void k1_precompute(const float* __restrict__ fe, const float* __restrict__ fb,
                              const float* __restrict__ W1, const float* __restrict__ b1) {
    int d = blockIdx.x;
    int h = threadIdx.x;
    if (blockIdx.x == 0) {
        for (int i = threadIdx.x; i < B_ * K_; i += H_) g_c[i] = 0.0f;
    }
    float acc = b1[h];
#pragma unroll
    for (int i = 0; i < 16; i++)
        acc = fmaf(fe[d * 16 + i], W1[(1 + i) * H_ + h], acc);
    acc = fmaf(fb[d], W1[17 * H_ + h], acc);
    g_G[d * H_ + h] = acc;
}

// ---------------- K2: main fused layer1+layer2+masked pooling ----------------
__global__ void k2_main(const float* __restrict__ x, const int* __restrict__ mask,
                        const float* __restrict__ W1, const float* __restrict__ W2,
                        const float* __restrict__ b2) {
    __shared__ __align__(16) float Gs[TD * 132];        // padded rows (132 floats)
    __shared__ __align__(16) float xs[TD * 65];         // x transposed, padded
    __shared__ __align__(16) float W2p[64 * 32];        // W2 paired: [hp][2k+(h&1)]
    __shared__ __align__(16) float w1s[H_];
    __shared__ float c_s[B_ * 17];                      // per-CTA pooled partials (padded)
    __shared__ unsigned short list[TD * B_];
    __shared__ unsigned long long maskbits[TD];
    __shared__ unsigned short cnt[TD];
    __shared__ unsigned short off[TD];
    __shared__ int nact_s;

    const int tid = threadIdx.x;
    const int d0  = blockIdx.x * TD;
    const int td  = min(TD, D_ - d0);

    // load G tile (coalesced, each G element touched once across the whole grid)
    for (int i = tid; i < td * H_; i += THR) {
        int dl = i >> 7, h = i & 127;
        Gs[dl * 132 + h] = g_G[(d0 + dl) * H_ + h];
    }
    // x tile, transposed into smem (read coalesced along d)
    for (int i = tid; i < B_ * td; i += THR) {
        int b = i / td, dl = i - b * td;
        xs[dl * 65 + b] = x[b * D_ + d0 + dl];
    }
    // W2 paired layout for even/odd-h f32x2 accumulation
    for (int i = tid; i < H_ * K_; i += THR) {
        int h = i >> 4, k = i & 15;
        W2p[(h >> 1) * 32 + ((k << 1) | (h & 1))] = W2[i];
    }
    if (tid < H_) w1s[tid] = W1[tid];                   // W1 row 0 (multiplies x)
    for (int i = tid; i < B_ * 17; i += THR) c_s[i] = 0.0f;

    // per-d mask ballot (d-sorted compaction -> warps see 1-2 distinct G rows)
    if (tid < TD) {
        unsigned long long bits = 0ULL;
        if (tid < td) {
#pragma unroll 8
            for (int b = 0; b < B_; b++)
                if (mask[b * D_ + d0 + tid]) bits |= (1ULL << b);
        }
        maskbits[tid] = bits;
        cnt[tid] = (unsigned short)__popcll(bits);
    }
    __syncthreads();
    if (tid == 0) {
        int r = 0;
        for (int dl = 0; dl < TD; dl++) { off[dl] = (unsigned short)r; r += cnt[dl]; }
        nact_s = r;
    }
    __syncthreads();
    if (tid < TD) {
        unsigned long long bits = maskbits[tid];
        int o = off[tid];
        while (bits) {
            int b = __ffsll(bits) - 1;
            bits &= bits - 1;
            list[o++] = (unsigned short)((tid << 8) | b);
        }
    }
    float b2r[K_];
#pragma unroll
    for (int k = 0; k < K_; k++) b2r[k] = b2[k];
    __syncthreads();

    const int nact = nact_s;
    for (int p = tid; p < nact; p += THR) {
        const unsigned e  = list[p];
        const int dl = e >> 8, b = e & 255;
        const float xv = xs[dl * 65 + b];
        const float* grow = &Gs[dl * 132];

        unsigned long long acc[K_];                    // halves: even-h / odd-h sums
#pragma unroll
        for (int k = 0; k < K_; k++) acc[k] = 0ULL;

#pragma unroll 4
        for (int h = 0; h < H_; h += 4) {
            float4 g4 = *(const float4*)(grow + h);
            float4 w4 = *(const float4*)(w1s + h);
            float e0 = fmaxf(fmaf(xv, w4.x, g4.x), 0.0f);
            float e1 = fmaxf(fmaf(xv, w4.y, g4.y), 0.0f);
            float e2 = fmaxf(fmaf(xv, w4.z, g4.z), 0.0f);
            float e3 = fmaxf(fmaf(xv, w4.w, g4.w), 0.0f);
            unsigned long long a01 = pk2(e0, e1);
            unsigned long long a23 = pk2(e2, e3);
            const unsigned long long* q0 =
                (const unsigned long long*)&W2p[(h >> 1) * 32];
            const unsigned long long* q1 =
                (const unsigned long long*)&W2p[((h >> 1) + 1) * 32];
#pragma unroll
            for (int k = 0; k < K_; k += 2) {
                ulonglong2 w0 = *(const ulonglong2*)(q0 + k);
                ulonglong2 w1 = *(const ulonglong2*)(q1 + k);
                fma2(acc[k],     a01, w0.x);
                fma2(acc[k + 1], a01, w0.y);
                fma2(acc[k],     a23, w1.x);
                fma2(acc[k + 1], a23, w1.y);
            }
        }
#pragma unroll
        for (int k = 0; k < K_; k++) {
            float2 v = unpk(acc[k]);
            float h2v = fmaxf(v.x + v.y + b2r[k], 0.0f);
            atomicAdd(&c_s[b * 17 + k], h2v);
        }
    }
    __syncthreads();
    for (int i = tid; i < B_ * K_; i += THR) {
        int b = i >> 4, k = i & 15;
        float v = c_s[b * 17 + k];
        if (v != 0.0f) atomicAdd(&g_c[i], v);
        else atomicAdd(&g_c[i], 0.0f);   // keep deterministic op count
    }
}

// ---------------- K3: encoder MLP ----------------
__global__ void k3a_enc1(const float* __restrict__ We1, const float* __restrict__ be1) {
    int b = blockIdx.x, e = threadIdx.x;               // 64 blocks x 256 threads
    float acc = be1[e];
#pragma unroll
    for (int k = 0; k < K_; k++)
        acc = fmaf(g_c[b * K_ + k], We1[k * E_ + e], acc);
    g_a1[b * E_ + e] = fmaxf(acc, 0.0f);
}

__global__ void k3b_enc2(const float* __restrict__ We2, const float* __restrict__ be2,
                         float* __restrict__ out) {
    int b = blockIdx.x, j = threadIdx.x;               // 64 blocks x 64 threads
    float acc = be2[j];
#pragma unroll 8
    for (int e = 0; e < E_; e++)
        acc = fmaf(g_a1[b * E_ + e], We2[e * 64 + j], acc);
    if (j < Z_) out[b * Z_ + j] = acc;                 // mu
    else        out[B_ * Z_ + b * Z_ + (j - Z_)] = acc; // logvar
}

// ---------------- launch ----------------
extern "C" void kernel_launch(void* const* d_in, const int* in_sizes, int n_in,
                              void* d_out, int out_size) {
    const float* x    = (const float*)d_in[0];
    const int*   mask = (const int*)  d_in[1];
    const float* fe   = (const float*)d_in[2];
    const float* fb   = (const float*)d_in[3];
    const float* W1   = (const float*)d_in[4];
    const float* b1   = (const float*)d_in[5];
    const float* W2   = (const float*)d_in[6];
    const float* b2   = (const float*)d_in[7];
    const float* We1  = (const float*)d_in[8];
    const float* be1  = (const float*)d_in[9];
    const float* We2  = (const float*)d_in[10];
    const float* be2  = (const float*)d_in[11];
    float* out = (float*)d_out;

    k1_precompute<<<D_, H_>>>(fe, fb, W1, b1);
    k2_main<<<(D_ + TD - 1) / TD, THR>>>(x, mask, W1, W2, b2);
    k3a_enc1<<<B_, E_>>>(We1, be1);
    k3b_enc2<<<B_, 64>>>(We2, be2, out);
}

// round 5
// speedup vs baseline: 1.0741x; 1.0741x over previous
#include <cuda_runtime.h>

#define B_   64
#define D_   25000
#define K_   16
#define H_   128
#define E_   256
#define Z_   32
#define TD   32
#define THR  256
#define NCTA ((D_ + TD - 1) / TD)   /* 782 */

// per-CTA pooled partials: [NCTA][B][K] — no global atomics anywhere
__device__ float g_cpart[NCTA * B_ * K_];

// ---------------- f32x2 helpers ----------------
__device__ __forceinline__ unsigned long long pk2(float lo, float hi) {
    unsigned long long r;
    asm("mov.b64 %0, {%1, %2};" : "=l"(r) : "f"(lo), "f"(hi));
    return r;
}
__device__ __forceinline__ void fma2(unsigned long long& d,
                                     unsigned long long a, unsigned long long b) {
    asm("fma.rn.f32x2 %0, %1, %2, %3;" : "=l"(d) : "l"(a), "l"(b), "l"(d));
}
__device__ __forceinline__ float2 unpk(unsigned long long v) {
    float2 r;
    asm("mov.b64 {%0, %1}, %2;" : "=f"(r.x), "=f"(r.y) : "l"(v));
    return r;
}

// shared-memory byte offsets (dynamic smem)
#define OFF_MBITS   0        /* u64[32]            256  */
#define OFF_GS      256      /* f32[32*132]      16896  */
#define OFF_XS      17152    /* f32[32*65]        8320  */
#define OFF_W2P     25472    /* f32[64*32]        8192  */
#define OFF_W1S0    33664    /* f32[128]           512  */
#define OFF_CW      34176    /* f32[8*64*17]     34816  */
#define OFF_B2S     68992    /* f32[16]             64  */
#define OFF_BLIST   69056    /* u8[32*32]         1024  */
#define OFF_OVF     70080    /* u16[32*32]        2048  */
#define OFF_CNT     72128    /* u8[32]              32  */
#define OFF_OVOFF   72160    /* u16[32]             64  */
#define OFF_NOVF    72224    /* int                  4  */
#define SMEM_BYTES  72240

// per-pair fused layer1(rank-1)+relu+layer2 (even/odd-h f32x2 accumulators)
__device__ __forceinline__ void pair_body(const float* __restrict__ grow,
                                          const float* __restrict__ w1s,
                                          const float* __restrict__ W2p,
                                          const float* __restrict__ b2s,
                                          float xv, float* __restrict__ h2)
{
    unsigned long long acc[K_];
#pragma unroll
    for (int k = 0; k < K_; k++) acc[k] = 0ULL;
#pragma unroll 4
    for (int h = 0; h < H_; h += 4) {
        float4 g4 = *(const float4*)(grow + h);
        float4 w4 = *(const float4*)(w1s + h);
        float e0 = fmaxf(fmaf(xv, w4.x, g4.x), 0.0f);
        float e1 = fmaxf(fmaf(xv, w4.y, g4.y), 0.0f);
        float e2 = fmaxf(fmaf(xv, w4.z, g4.z), 0.0f);
        float e3 = fmaxf(fmaf(xv, w4.w, g4.w), 0.0f);
        unsigned long long a01 = pk2(e0, e1);
        unsigned long long a23 = pk2(e2, e3);
        const unsigned long long* q0 = (const unsigned long long*)&W2p[(h >> 1) * 32];
        const unsigned long long* q1 = (const unsigned long long*)&W2p[((h >> 1) + 1) * 32];
#pragma unroll
        for (int k = 0; k < K_; k += 2) {
            ulonglong2 w0 = *(const ulonglong2*)(q0 + k);
            ulonglong2 w1 = *(const ulonglong2*)(q1 + k);
            fma2(acc[k],     a01, w0.x);
            fma2(acc[k + 1], a01, w0.y);
            fma2(acc[k],     a23, w1.x);
            fma2(acc[k + 1], a23, w1.y);
        }
    }
#pragma unroll
    for (int k = 0; k < K_; k++) {
        float2 v = unpk(acc[k]);
        h2[k] = fmaxf(v.x + v.y + b2s[k], 0.0f);
    }
}

// ---------------- K2: fused G-precompute + layer1+layer2 + masked pooling ----------------
__global__ void __launch_bounds__(THR)
k2_main(const float* __restrict__ x, const int* __restrict__ mask,
        const float* __restrict__ fe, const float* __restrict__ fb,
        const float* __restrict__ W1, const float* __restrict__ b1,
        const float* __restrict__ W2, const float* __restrict__ b2)
{
    extern __shared__ __align__(16) char sm[];
    unsigned long long* mbits = (unsigned long long*)(sm + OFF_MBITS);
    float* Gs  = (float*)(sm + OFF_GS);
    float* xs  = (float*)(sm + OFF_XS);
    float* W2p = (float*)(sm + OFF_W2P);
    float* w1s = (float*)(sm + OFF_W1S0);
    float* cw  = (float*)(sm + OFF_CW);
    float* b2s = (float*)(sm + OFF_B2S);
    unsigned char*  blist   = (unsigned char*) (sm + OFF_BLIST);
    unsigned short* ovf     = (unsigned short*)(sm + OFF_OVF);
    unsigned char*  cnt_all = (unsigned char*) (sm + OFF_CNT);
    unsigned short* ovoff   = (unsigned short*)(sm + OFF_OVOFF);
    int* novf_s = (int*)(sm + OFF_NOVF);

    // build-phase scratch aliased inside cw (zeroed later)
    float* W1s = cw;            // [18][128]
    float* fes = cw + 2304;     // [TD][16]
    float* fbs = cw + 2816;     // [TD]
    float* b1s = cw + 2848;     // [128]

    const int tid  = threadIdx.x;
    const int d0   = blockIdx.x * TD;
    const int td   = min(TD, D_ - d0);
    const int w    = tid >> 5;
    const int lane = tid & 31;

    // ---- cooperative loads ----
    for (int i = tid; i < 18 * H_; i += THR) W1s[i] = W1[i];
    for (int i = tid; i < td * K_; i += THR) fes[i] = fe[d0 * K_ + i];
    if (tid < td) fbs[tid] = fb[d0 + tid];
    if (tid < H_) { b1s[tid] = b1[tid]; w1s[tid] = W1[tid]; }
    if (tid < K_) b2s[tid] = b2[tid];
    for (int i = tid; i < H_ * K_; i += THR) {
        int h = i >> 4, k = i & 15;
        W2p[(h >> 1) * 32 + ((k << 1) | (h & 1))] = W2[i];
    }
    for (int i = tid; i < B_ * td; i += THR) {
        int b = i / td, dl = i - b * td;
        xs[dl * 65 + b] = x[b * D_ + d0 + dl];
    }
    __syncthreads();

    // ---- fused k1: G tile in smem ----
    for (int i = tid; i < td * H_; i += THR) {
        int dl = i >> 7, h = i & 127;
        float acc = b1s[h];
        const float* fr = fes + dl * K_;
#pragma unroll
        for (int j = 0; j < K_; j++) acc = fmaf(fr[j], W1s[(1 + j) * H_ + h], acc);
        acc = fmaf(fbs[dl], W1s[17 * H_ + h], acc);
        Gs[dl * 132 + h] = acc;
    }

    // ---- mask ballots + main-list ranks (lanes = b, b+32) ----
#pragma unroll
    for (int q = 0; q < 4; q++) {
        int dl = w * 4 + q;
        int onlo = 0, onhi = 0;
        if (dl < td) {
            onlo = mask[lane * D_ + d0 + dl];
            onhi = mask[(lane + 32) * D_ + d0 + dl];
        }
        unsigned lo = __ballot_sync(0xffffffffu, onlo != 0);
        unsigned hi = __ballot_sync(0xffffffffu, onhi != 0);
        if (dl < td) {
            if (lane == 0) {
                mbits[dl] = ((unsigned long long)hi << 32) | lo;
                cnt_all[dl] = (unsigned char)(__popc(lo) + __popc(hi));
            }
            if (onlo) {
                int r = __popc(lo & ((1u << lane) - 1u));
                if (r < 32) blist[dl * 32 + r] = (unsigned char)lane;
            }
            if (onhi) {
                int r = __popc(lo) + __popc(hi & ((1u << lane) - 1u));
                if (r < 32) blist[dl * 32 + r] = (unsigned char)(32 + lane);
            }
        } else if (lane == 0) {
            mbits[dl] = 0ULL; cnt_all[dl] = 0;
        }
    }
    __syncthreads();

    // ---- overflow offsets (exclusive scan) + zero cw ----
    if (tid == 0) {
        int nov = 0;
        for (int dl = 0; dl < TD; dl++) {
            ovoff[dl] = (unsigned short)nov;
            int n = cnt_all[dl];
            nov += (n > 32) ? (n - 32) : 0;
        }
        *novf_s = nov;
    }
    for (int i = tid; i < 8 * B_ * 17; i += THR) cw[i] = 0.0f;
    __syncthreads();

    // ---- fill overflow list (entries with rank >= 32) ----
#pragma unroll
    for (int q = 0; q < 4; q++) {
        int dl = w * 4 + q;
        if (dl < td) {
            unsigned long long bits = mbits[dl];
            unsigned lo = (unsigned)bits, hi = (unsigned)(bits >> 32);
            if ((lo >> lane) & 1u) {
                int r = __popc(lo & ((1u << lane) - 1u));
                if (r >= 32) ovf[ovoff[dl] + r - 32] = (unsigned short)((dl << 8) | lane);
            }
            if ((hi >> lane) & 1u) {
                int r = __popc(lo) + __popc(hi & ((1u << lane) - 1u));
                if (r >= 32) ovf[ovoff[dl] + r - 32] = (unsigned short)((dl << 8) | (32 + lane));
            }
        }
    }
    __syncthreads();

    // ---- main passes: warp-per-d, lanes = distinct active b → race-free smem RMW ----
    float* cwb = cw + w * (B_ * 17);
#pragma unroll 1
    for (int q = 0; q < 4; q++) {
        int dl = w * 4 + q;
        if (dl >= td) continue;
        int nm = min((int)cnt_all[dl], 32);
        if (lane < nm) {
            int b = blist[dl * 32 + lane];
            float h2[K_];
            pair_body(Gs + dl * 132, w1s, W2p, b2s, xs[dl * 65 + b], h2);
            float* cp = cwb + b * 17;
#pragma unroll
            for (int k = 0; k < K_; k++) cp[k] += h2[k];
        }
    }

    // ---- overflow passes: cross-d packed; duplicates possible → smem atomics (low volume) ----
    const int novf = *novf_s;
    for (int p = tid; p < novf; p += THR) {
        int e = ovf[p];
        int dl = e >> 8, b = e & 255;
        float h2[K_];
        pair_body(Gs + dl * 132, w1s, W2p, b2s, xs[dl * 65 + b], h2);
        float* cp = cwb + b * 17;
#pragma unroll
        for (int k = 0; k < K_; k++) atomicAdd(cp + k, h2[k]);
    }
    __syncthreads();

    // ---- reduce over 8 warp-buffers, write per-CTA partial ----
    for (int i = tid; i < B_ * K_; i += THR) {
        int b = i >> 4, k = i & 15;
        float s = 0.0f;
#pragma unroll
        for (int ww = 0; ww < 8; ww++) s += cw[ww * (B_ * 17) + b * 17 + k];
        g_cpart[blockIdx.x * (B_ * K_) + i] = s;
    }
}

// ---------------- K3: partial-reduce + full encoder MLP, one block per b ----------------
__global__ void __launch_bounds__(256)
k3_enc(const float* __restrict__ We1, const float* __restrict__ be1,
       const float* __restrict__ We2, const float* __restrict__ be2,
       float* __restrict__ out)
{
    __shared__ float cpart[16 * 17];
    __shared__ float cfin[K_];
    __shared__ float a1s[E_];
    __shared__ float ps[4 * 65];
    const int b = blockIdx.x, t = threadIdx.x;

    // reduce 782 per-CTA partials: 16 groups x 16 k
    {
        int k = t & 15, g = t >> 4;
        float s = 0.0f;
        for (int cta = g; cta < NCTA; cta += 16)
            s += g_cpart[cta * (B_ * K_) + b * K_ + k];
        cpart[g * 17 + k] = s;
    }
    __syncthreads();
    if (t < K_) {
        float v = 0.0f;
#pragma unroll
        for (int g = 0; g < 16; g++) v += cpart[g * 17 + t];
        cfin[t] = v;
    }
    __syncthreads();

    // encoder layer 1: thread t -> hidden unit e
    {
        float acc = be1[t];
#pragma unroll
        for (int k = 0; k < K_; k++) acc = fmaf(cfin[k], We1[k * E_ + t], acc);
        a1s[t] = fmaxf(acc, 0.0f);
    }
    __syncthreads();

    // encoder layer 2: 64 j x 4 e-groups, then reduce
    {
        int j = t & 63, g = t >> 6;
        float p = 0.0f;
#pragma unroll 8
        for (int e = g * 64; e < g * 64 + 64; e++)
            p = fmaf(a1s[e], We2[e * 64 + j], p);
        ps[g * 65 + j] = p;
    }
    __syncthreads();
    if (t < 64) {
        float v = be2[t] + ps[t] + ps[65 + t] + ps[130 + t] + ps[195 + t];
        if (t < Z_) out[b * Z_ + t] = v;                      // mu
        else        out[B_ * Z_ + b * Z_ + (t - Z_)] = v;     // logvar
    }
}

// ---------------- launch ----------------
extern "C" void kernel_launch(void* const* d_in, const int* in_sizes, int n_in,
                              void* d_out, int out_size) {
    const float* x    = (const float*)d_in[0];
    const int*   mask = (const int*)  d_in[1];
    const float* fe   = (const float*)d_in[2];
    const float* fb   = (const float*)d_in[3];
    const float* W1   = (const float*)d_in[4];
    const float* b1   = (const float*)d_in[5];
    const float* W2   = (const float*)d_in[6];
    const float* b2   = (const float*)d_in[7];
    const float* We1  = (const float*)d_in[8];
    const float* be1  = (const float*)d_in[9];
    const float* We2  = (const float*)d_in[10];
    const float* be2  = (const float*)d_in[11];
    float* out = (float*)d_out;

    cudaFuncSetAttribute(k2_main, cudaFuncAttributeMaxDynamicSharedMemorySize, SMEM_BYTES);
    k2_main<<<NCTA, THR, SMEM_BYTES>>>(x, mask, fe, fb, W1, b1, W2, b2);
    k3_enc<<<B_, 256>>>(We1, be1, We2, be2, out);
}

// round 8
// speedup vs baseline: 1.1858x; 1.1040x over previous
#include <cuda_runtime.h>

#define B_   64
#define D_   25000
#define K_   16
#define H_   128
#define E_   256
#define Z_   32
#define TD   32
#define THR  256
#define NCTA ((D_ + TD - 1) / TD)   /* 782 */
#define NCP  784                    /* padded cta dim */

__device__ float g_cpart[B_ * K_ * NCP];   // transposed partials [b*16+k][cta]

// ---------------- f32x2 helpers ----------------
__device__ __forceinline__ unsigned long long pk2(float lo, float hi) {
    unsigned long long r;
    asm("mov.b64 %0, {%1, %2};" : "=l"(r) : "f"(lo), "f"(hi));
    return r;
}
__device__ __forceinline__ void fma2(unsigned long long& d,
                                     unsigned long long a, unsigned long long b) {
    asm("fma.rn.f32x2 %0, %1, %2, %3;" : "=l"(d) : "l"(a), "l"(b), "l"(d));
}
__device__ __forceinline__ float2 unpk(unsigned long long v) {
    float2 r;
    asm("mov.b64 {%0, %1}, %2;" : "=f"(r.x), "=f"(r.y) : "l"(v));
    return r;
}

// conflict-free c accumulation index (b and b+32 land in different banks)
#define CWSTR 1104
#define CIDX(b) ((b) * 17 + (((b) >> 5) << 3))

// shared-memory byte offsets
#define OFF_MBITS   0        /* u64[32]            256  */
#define OFF_GS      256      /* f32[32*132]      16896  */
#define OFF_XS      17152    /* f32[32*65]        8320  */
#define OFF_W2P     25472    /* f32[64*32]        8192  */
#define OFF_W1S0    33664    /* f32[128]           512  */
#define OFF_CW      34176    /* f32[8*1104]      35328  */
#define OFF_B2S     69504    /* f32[16]             64  */
#define OFF_BLIST   69568    /* u8[32*32]         1024  */
#define OFF_OVF     70592    /* u16[32*32]        2048  */
#define OFF_CNT     72640    /* u8[32]              32  */
#define OFF_OVOFF   72672    /* u16[32]             64  */
#define OFF_NOVF    72736    /* int                  4  */
#define SMEM_BYTES  72768

// dual-pair fused layer1(rank-1)+relu+layer2: two d's share all W2/w1 loads
__device__ __forceinline__ void pair2_body(const float* __restrict__ gA,
                                           const float* __restrict__ gB,
                                           const float* __restrict__ w1s,
                                           const float* __restrict__ W2p,
                                           const float* __restrict__ b2s,
                                           float xvA, float xvB,
                                           float* __restrict__ h2A,
                                           float* __restrict__ h2B)
{
    unsigned long long accA[K_], accB[K_];
#pragma unroll
    for (int k = 0; k < K_; k++) { accA[k] = 0ULL; accB[k] = 0ULL; }
#pragma unroll 4
    for (int h = 0; h < H_; h += 4) {
        float4 a4 = *(const float4*)(gA + h);
        float4 c4 = *(const float4*)(gB + h);
        float4 w4 = *(const float4*)(w1s + h);
        float eA0 = fmaxf(fmaf(xvA, w4.x, a4.x), 0.0f);
        float eA1 = fmaxf(fmaf(xvA, w4.y, a4.y), 0.0f);
        float eA2 = fmaxf(fmaf(xvA, w4.z, a4.z), 0.0f);
        float eA3 = fmaxf(fmaf(xvA, w4.w, a4.w), 0.0f);
        float eB0 = fmaxf(fmaf(xvB, w4.x, c4.x), 0.0f);
        float eB1 = fmaxf(fmaf(xvB, w4.y, c4.y), 0.0f);
        float eB2 = fmaxf(fmaf(xvB, w4.z, c4.z), 0.0f);
        float eB3 = fmaxf(fmaf(xvB, w4.w, c4.w), 0.0f);
        unsigned long long aA01 = pk2(eA0, eA1);
        unsigned long long aA23 = pk2(eA2, eA3);
        unsigned long long aB01 = pk2(eB0, eB1);
        unsigned long long aB23 = pk2(eB2, eB3);
        const unsigned long long* q0 = (const unsigned long long*)&W2p[(h >> 1) * 32];
        const unsigned long long* q1 = (const unsigned long long*)&W2p[((h >> 1) + 1) * 32];
#pragma unroll
        for (int k = 0; k < K_; k += 2) {
            ulonglong2 w0 = *(const ulonglong2*)(q0 + k);
            ulonglong2 w1 = *(const ulonglong2*)(q1 + k);
            fma2(accA[k],     aA01, w0.x);
            fma2(accA[k + 1], aA01, w0.y);
            fma2(accA[k],     aA23, w1.x);
            fma2(accA[k + 1], aA23, w1.y);
            fma2(accB[k],     aB01, w0.x);
            fma2(accB[k + 1], aB01, w0.y);
            fma2(accB[k],     aB23, w1.x);
            fma2(accB[k + 1], aB23, w1.y);
        }
    }
#pragma unroll
    for (int k = 0; k < K_; k++) {
        float2 va = unpk(accA[k]);
        float2 vb = unpk(accB[k]);
        h2A[k] = fmaxf(va.x + va.y + b2s[k], 0.0f);
        h2B[k] = fmaxf(vb.x + vb.y + b2s[k], 0.0f);
    }
}

// ---------------- K2: fused G-precompute + layer1+layer2 + masked pooling ----------------
__global__ void __launch_bounds__(THR, 2)
k2_main(const float* __restrict__ x, const int* __restrict__ mask,
        const float* __restrict__ fe, const float* __restrict__ fb,
        const float* __restrict__ W1, const float* __restrict__ b1,
        const float* __restrict__ W2, const float* __restrict__ b2)
{
    extern __shared__ __align__(16) char sm[];
    unsigned long long* mbits = (unsigned long long*)(sm + OFF_MBITS);
    float* Gs  = (float*)(sm + OFF_GS);
    float* xs  = (float*)(sm + OFF_XS);
    float* W2p = (float*)(sm + OFF_W2P);
    float* w1s = (float*)(sm + OFF_W1S0);
    float* cw  = (float*)(sm + OFF_CW);
    float* b2s = (float*)(sm + OFF_B2S);
    unsigned char*  blist   = (unsigned char*) (sm + OFF_BLIST);
    unsigned short* ovf     = (unsigned short*)(sm + OFF_OVF);
    unsigned char*  cnt_all = (unsigned char*) (sm + OFF_CNT);
    unsigned short* ovoff   = (unsigned short*)(sm + OFF_OVOFF);
    int* novf_s = (int*)(sm + OFF_NOVF);

    // build-phase scratch aliased inside cw (zeroed later)
    float* W1s = cw;            // [18][128]
    float* fes = cw + 2304;     // [TD][16]
    float* fbs = cw + 2816;     // [TD]
    float* b1s = cw + 2848;     // [128]

    const int tid  = threadIdx.x;
    const int d0   = blockIdx.x * TD;
    const int td   = min(TD, D_ - d0);
    const int w    = tid >> 5;
    const int lane = tid & 31;

    // ---- cooperative loads ----
    for (int i = tid; i < 18 * H_; i += THR) W1s[i] = W1[i];
    for (int i = tid; i < td * K_; i += THR) fes[i] = fe[d0 * K_ + i];
    if (tid < td) fbs[tid] = fb[d0 + tid];
    if (tid < H_) { b1s[tid] = b1[tid]; w1s[tid] = W1[tid]; }
    if (tid < K_) b2s[tid] = b2[tid];
    for (int i = tid; i < H_ * K_; i += THR) {
        int h = i >> 4, k = i & 15;
        W2p[(h >> 1) * 32 + ((k << 1) | (h & 1))] = W2[i];
    }
    for (int i = tid; i < B_ * td; i += THR) {
        int b = i / td, dl = i - b * td;
        xs[dl * 65 + b] = x[b * D_ + d0 + dl];
    }
    __syncthreads();

    // ---- fused k1: G tile in smem ----
    for (int i = tid; i < td * H_; i += THR) {
        int dl = i >> 7, h = i & 127;
        float acc = b1s[h];
        const float* fr = fes + dl * K_;
#pragma unroll
        for (int j = 0; j < K_; j++) acc = fmaf(fr[j], W1s[(1 + j) * H_ + h], acc);
        acc = fmaf(fbs[dl], W1s[17 * H_ + h], acc);
        Gs[dl * 132 + h] = acc;
    }

    // ---- mask ballots + main-list ranks (lanes = b, b+32) ----
#pragma unroll
    for (int q = 0; q < 4; q++) {
        int dl = w * 4 + q;
        int onlo = 0, onhi = 0;
        if (dl < td) {
            onlo = mask[lane * D_ + d0 + dl];
            onhi = mask[(lane + 32) * D_ + d0 + dl];
        }
        unsigned lo = __ballot_sync(0xffffffffu, onlo != 0);
        unsigned hi = __ballot_sync(0xffffffffu, onhi != 0);
        if (dl < td) {
            if (lane == 0) {
                mbits[dl] = ((unsigned long long)hi << 32) | lo;
                cnt_all[dl] = (unsigned char)(__popc(lo) + __popc(hi));
            }
            if (onlo) {
                int r = __popc(lo & ((1u << lane) - 1u));
                if (r < 32) blist[dl * 32 + r] = (unsigned char)lane;
            }
            if (onhi) {
                int r = __popc(lo) + __popc(hi & ((1u << lane) - 1u));
                if (r < 32) blist[dl * 32 + r] = (unsigned char)(32 + lane);
            }
        } else if (lane == 0) {
            mbits[dl] = 0ULL; cnt_all[dl] = 0;
        }
    }
    __syncthreads();

    // ---- overflow offsets (exclusive scan) + zero cw ----
    if (tid == 0) {
        int nov = 0;
        for (int dl = 0; dl < TD; dl++) {
            ovoff[dl] = (unsigned short)nov;
            int n = cnt_all[dl];
            nov += (n > 32) ? (n - 32) : 0;
        }
        *novf_s = nov;
    }
    for (int i = tid; i < 8 * CWSTR; i += THR) cw[i] = 0.0f;
    __syncthreads();

    // ---- fill overflow list (entries with rank >= 32) ----
#pragma unroll
    for (int q = 0; q < 4; q++) {
        int dl = w * 4 + q;
        if (dl < td) {
            unsigned long long bits = mbits[dl];
            unsigned lo = (unsigned)bits, hi = (unsigned)(bits >> 32);
            if ((lo >> lane) & 1u) {
                int r = __popc(lo & ((1u << lane) - 1u));
                if (r >= 32) ovf[ovoff[dl] + r - 32] = (unsigned short)((dl << 8) | lane);
            }
            if ((hi >> lane) & 1u) {
                int r = __popc(lo) + __popc(hi & ((1u << lane) - 1u));
                if (r >= 32) ovf[ovoff[dl] + r - 32] = (unsigned short)((dl << 8) | (32 + lane));
            }
        }
    }
    __syncthreads();

    // ---- main: 2 dual-d passes per warp; lanes = distinct active b → race-free smem RMW ----
    float* cwb = cw + w * CWSTR;
    float h2A[K_], h2B[K_];
#pragma unroll 1
    for (int q = 0; q < 2; q++) {
        const int dlA = w * 4 + q * 2;
        const int dlB = dlA + 1;
        const int nmA = (dlA < td) ? min((int)cnt_all[dlA], 32) : 0;
        const int nmB = (dlB < td) ? min((int)cnt_all[dlB], 32) : 0;
        const bool onA = lane < nmA, onB = lane < nmB;
        const int bA = onA ? (int)blist[dlA * 32 + lane] : 0;
        const int bB = onB ? (int)blist[dlB * 32 + lane] : 0;
        const float xvA = onA ? xs[dlA * 65 + bA] : 0.0f;
        const float xvB = onB ? xs[dlB * 65 + bB] : 0.0f;

        pair2_body(Gs + dlA * 132, Gs + dlB * 132, w1s, W2p, b2s, xvA, xvB, h2A, h2B);

        if (onA) {
            float* cp = cwb + CIDX(bA);
#pragma unroll
            for (int k = 0; k < K_; k++) cp[k] += h2A[k];
        }
        __syncwarp();
        if (onB) {
            float* cp = cwb + CIDX(bB);
#pragma unroll
            for (int k = 0; k < K_; k++) cp[k] += h2B[k];
        }
        __syncwarp();
    }

    // ---- overflow: cross-d packed, 2 entries per thread; duplicates possible → smem atomics ----
    const int novf = *novf_s;
    const int half = (novf + 1) >> 1;
    for (int p = tid; p < half; p += THR) {
        const int eA = ovf[p];
        const int pb = p + half;
        const bool onB = pb < novf;
        const int eB = onB ? ovf[pb] : eA;
        const int dlA = eA >> 8, bA = eA & 255;
        const int dlB = eB >> 8, bB = eB & 255;
        pair2_body(Gs + dlA * 132, Gs + dlB * 132, w1s, W2p, b2s,
                   xs[dlA * 65 + bA], xs[dlB * 65 + bB], h2A, h2B);
        float* cpA = cwb + CIDX(bA);
#pragma unroll
        for (int k = 0; k < K_; k++) atomicAdd(cpA + k, h2A[k]);
        if (onB) {
            float* cpB = cwb + CIDX(bB);
#pragma unroll
            for (int k = 0; k < K_; k++) atomicAdd(cpB + k, h2B[k]);
        }
    }
    __syncthreads();

    // ---- reduce 8 warp-buffers → transposed per-CTA partial ----
    for (int i = tid; i < B_ * K_; i += THR) {
        int b = i >> 4, k = i & 15;
        float s = 0.0f;
#pragma unroll
        for (int ww = 0; ww < 8; ww++) s += cw[ww * CWSTR + CIDX(b) + k];
        g_cpart[i * NCP + blockIdx.x] = s;
    }
}

// ---------------- K3: coalesced partial-reduce + encoder MLP, one block per b ----------------
__global__ void __launch_bounds__(256)
k3_enc(const float* __restrict__ We1, const float* __restrict__ be1,
       const float* __restrict__ We2, const float* __restrict__ be2,
       float* __restrict__ out)
{
    __shared__ float cfin[K_];
    __shared__ float a1s[E_];
    __shared__ float ps[4 * 65];
    const int b = blockIdx.x, t = threadIdx.x;
    const int w = t >> 5, lane = t & 31;

    // warp w reduces k = 2w, 2w+1 over 782 CTA partials (coalesced)
#pragma unroll
    for (int j = 0; j < 2; j++) {
        int k = w * 2 + j;
        const float* src = g_cpart + (b * K_ + k) * NCP;
        float s = 0.0f;
        for (int c = lane; c < NCTA; c += 32) s += src[c];
#pragma unroll
        for (int o = 16; o; o >>= 1) s += __shfl_xor_sync(0xffffffffu, s, o);
        if (lane == 0) cfin[k] = s;
    }
    __syncthreads();

    // encoder layer 1: thread t -> hidden unit e
    {
        float acc = be1[t];
#pragma unroll
        for (int k = 0; k < K_; k++) acc = fmaf(cfin[k], We1[k * E_ + t], acc);
        a1s[t] = fmaxf(acc, 0.0f);
    }
    __syncthreads();

    // encoder layer 2: 64 j x 4 e-groups, then reduce
    {
        int j = t & 63, g = t >> 6;
        float p = 0.0f;
#pragma unroll 8
        for (int e = g * 64; e < g * 64 + 64; e++)
            p = fmaf(a1s[e], We2[e * 64 + j], p);
        ps[g * 65 + j] = p;
    }
    __syncthreads();
    if (t < 64) {
        float v = be2[t] + ps[t] + ps[65 + t] + ps[130 + t] + ps[195 + t];
        if (t < Z_) out[b * Z_ + t] = v;                      // mu
        else        out[B_ * Z_ + b * Z_ + (t - Z_)] = v;     // logvar
    }
}

// nop markers: shift launch-index parity so ncu (-s 5 -c 1) profiles k2_main
__global__ void nop_k() {}

// ---------------- launch ----------------
extern "C" void kernel_launch(void* const* d_in, const int* in_sizes, int n_in,
                              void* d_out, int out_size) {
    const float* x    = (const float*)d_in[0];
    const int*   mask = (const int*)  d_in[1];
    const float* fe   = (const float*)d_in[2];
    const float* fb   = (const float*)d_in[3];
    const float* W1   = (const float*)d_in[4];
    const float* b1   = (const float*)d_in[5];
    const float* W2   = (const float*)d_in[6];
    const float* b2   = (const float*)d_in[7];
    const float* We1  = (const float*)d_in[8];
    const float* be1  = (const float*)d_in[9];
    const float* We2  = (const float*)d_in[10];
    const float* be2  = (const float*)d_in[11];
    float* out = (float*)d_out;

    cudaFuncSetAttribute(k2_main, cudaFuncAttributeMaxDynamicSharedMemorySize, SMEM_BYTES);
    nop_k<<<1, 32>>>();
    k2_main<<<NCTA, THR, SMEM_BYTES>>>(x, mask, fe, fb, W1, b1, W2, b2);
    k3_enc<<<B_, 256>>>(We1, be1, We2, be2, out);
    nop_k<<<1, 32>>>();
}